// round 1
// baseline (speedup 1.0000x reference)
#include <cuda_runtime.h>
#include <math.h>

#define NB 2
#define NT 2048
#define ND 2048
#define NH 16
#define DH 128
#define NM (NB*NT)            // 4096 rows

// Scratch (static device globals: allowed; no cudaMalloc anywhere)
__device__ float g_qkv[(size_t)NM * 3 * ND];      // [M, 6144]
__device__ float g_q[(size_t)NB*NH*NT*DH];        // [B,H,T,Dh]
__device__ float g_k[(size_t)NB*NH*NT*DH];
__device__ float g_v[(size_t)NB*NH*NT*DH];
__device__ float g_att[(size_t)NM * ND];          // [B,T,D] attention output

// ---------------------------------------------------------------------------
// Tiled SGEMM: C[m,n] = sum_k A[m,k] * Bw[n,k]   (both operands K-major)
// BM=BN=128, BK=16, 256 threads, 8x8 microtile per thread.
// ---------------------------------------------------------------------------
__global__ __launch_bounds__(256)
void gemm_kn_kernel(const float* __restrict__ A, const float* __restrict__ Bw,
                    float* __restrict__ C, int M, int N, int K)
{
    __shared__ float As[16][132];
    __shared__ float Bs[16][132];

    const int tid = threadIdx.x;
    const int m0 = blockIdx.y * 128;
    const int n0 = blockIdx.x * 128;
    const int ty = tid >> 4;        // 0..15
    const int tx = tid & 15;        // 0..15

    float acc[8][8];
#pragma unroll
    for (int i = 0; i < 8; i++)
#pragma unroll
        for (int j = 0; j < 8; j++) acc[i][j] = 0.0f;

    const int lr = tid >> 2;          // 0..63
    const int lc = (tid & 3) << 2;    // 0,4,8,12

    for (int k0 = 0; k0 < K; k0 += 16) {
        float4 a0 = *(const float4*)&A [(size_t)(m0 + lr     ) * K + k0 + lc];
        float4 a1 = *(const float4*)&A [(size_t)(m0 + lr + 64) * K + k0 + lc];
        float4 b0 = *(const float4*)&Bw[(size_t)(n0 + lr     ) * K + k0 + lc];
        float4 b1 = *(const float4*)&Bw[(size_t)(n0 + lr + 64) * K + k0 + lc];

        As[lc+0][lr]    = a0.x; As[lc+1][lr]    = a0.y; As[lc+2][lr]    = a0.z; As[lc+3][lr]    = a0.w;
        As[lc+0][lr+64] = a1.x; As[lc+1][lr+64] = a1.y; As[lc+2][lr+64] = a1.z; As[lc+3][lr+64] = a1.w;
        Bs[lc+0][lr]    = b0.x; Bs[lc+1][lr]    = b0.y; Bs[lc+2][lr]    = b0.z; Bs[lc+3][lr]    = b0.w;
        Bs[lc+0][lr+64] = b1.x; Bs[lc+1][lr+64] = b1.y; Bs[lc+2][lr+64] = b1.z; Bs[lc+3][lr+64] = b1.w;
        __syncthreads();

#pragma unroll
        for (int kk = 0; kk < 16; kk++) {
            float4 av0 = *(const float4*)&As[kk][ty*8];
            float4 av1 = *(const float4*)&As[kk][ty*8 + 4];
            float4 bv0 = *(const float4*)&Bs[kk][tx*8];
            float4 bv1 = *(const float4*)&Bs[kk][tx*8 + 4];
            float ar[8] = {av0.x, av0.y, av0.z, av0.w, av1.x, av1.y, av1.z, av1.w};
            float br[8] = {bv0.x, bv0.y, bv0.z, bv0.w, bv1.x, bv1.y, bv1.z, bv1.w};
#pragma unroll
            for (int i = 0; i < 8; i++)
#pragma unroll
                for (int j = 0; j < 8; j++)
                    acc[i][j] = fmaf(ar[i], br[j], acc[i][j]);
        }
        __syncthreads();
    }

#pragma unroll
    for (int i = 0; i < 8; i++) {
        float4 c0 = make_float4(acc[i][0], acc[i][1], acc[i][2], acc[i][3]);
        float4 c1 = make_float4(acc[i][4], acc[i][5], acc[i][6], acc[i][7]);
        size_t off = (size_t)(m0 + ty*8 + i) * N + n0 + tx*8;
        *(float4*)&C[off]     = c0;
        *(float4*)&C[off + 4] = c1;
    }
}

// ---------------------------------------------------------------------------
// RoPE + split into per-head layout [B,H,T,Dh]
// one thread per (b,t,h,pair)
// ---------------------------------------------------------------------------
__global__ __launch_bounds__(256)
void rope_split_kernel(const float* __restrict__ qkv,
                       float* __restrict__ q, float* __restrict__ k,
                       float* __restrict__ v)
{
    int idx = blockIdx.x * blockDim.x + threadIdx.x;    // 0 .. B*T*H*64-1
    int i = idx & 63;
    int h = (idx >> 6) & 15;
    int t = (idx >> 10) & 2047;
    int b = idx >> 21;

    int m = b * NT + t;
    const float* base = qkv + (size_t)m * (3 * ND);
    int col = h * DH + 2 * i;

    float q0 = base[col],          q1 = base[col + 1];
    float k0 = base[ND + col],     k1 = base[ND + col + 1];
    float v0 = base[2*ND + col],   v1 = base[2*ND + col + 1];

    float fr = expf(-logf(10000.0f) * (2.0f * (float)i) / (float)DH);
    float ang = (float)t * fr;
    float sn = sinf(ang), cs = cosf(ang);

    size_t o = ((size_t)(b * NH + h) * NT + t) * DH + 2 * i;
    q[o]     = q0 * cs - q1 * sn;
    q[o + 1] = q1 * cs + q0 * sn;
    k[o]     = k0 * cs - k1 * sn;
    k[o + 1] = k1 * cs + k0 * sn;
    v[o]     = v0;
    v[o + 1] = v1;
}

// ---------------------------------------------------------------------------
// Flash-style causal attention.
// One block per (q_tile of 64, h, b). 256 threads.
// Online softmax; O accumulators in registers (4 rows x 8 cols per thread).
// Output written directly in [B,T,D] layout (= GEMM2's A operand).
// ---------------------------------------------------------------------------
struct AttnSmem {
    float Qs[64][132];
    float Ks[64][132];
    float Vs[64][132];
    float Ss[64][68];
    float mrow[64];
    float lrow[64];
    float frow[64];
};

__global__ __launch_bounds__(256)
void attn_kernel(const float* __restrict__ Q, const float* __restrict__ K,
                 const float* __restrict__ V, float* __restrict__ O)
{
    extern __shared__ unsigned char smem_bytes[];
    AttnSmem& S = *reinterpret_cast<AttnSmem*>(smem_bytes);

    const int tid = threadIdx.x;
    const int qt = blockIdx.x;      // query tile
    const int h  = blockIdx.y;
    const int b  = blockIdx.z;

    const float scale = 0.08838834764831845f;   // 1/sqrt(128)
    const size_t head_base = (size_t)(b * NH + h) * NT * DH;

    // Load Q tile (scaled)
    {
        size_t qbase = head_base + (size_t)qt * 64 * DH;
#pragma unroll
        for (int u = 0; u < 8; u++) {
            int e = tid + u * 256;          // float4 index, 0..2047
            int r = e >> 5;
            int c4 = (e & 31) * 4;
            float4 qv = *(const float4*)&Q[qbase + (size_t)r * DH + c4];
            qv.x *= scale; qv.y *= scale; qv.z *= scale; qv.w *= scale;
            *(float4*)&S.Qs[r][c4] = qv;
        }
    }
    if (tid < 64) { S.mrow[tid] = -1e30f; S.lrow[tid] = 0.0f; S.frow[tid] = 0.0f; }

    const int sy = tid >> 4, sx = tid & 15;     // for S compute (4x4) and O (4 rows x 8 cols)
    float accO[4][8];
#pragma unroll
    for (int i = 0; i < 4; i++)
#pragma unroll
        for (int j = 0; j < 8; j++) accO[i][j] = 0.0f;

    for (int kt = 0; kt <= qt; kt++) {
        // Load K, V tiles
        size_t kbase = head_base + (size_t)kt * 64 * DH;
#pragma unroll
        for (int u = 0; u < 8; u++) {
            int e = tid + u * 256;
            int r = e >> 5;
            int c4 = (e & 31) * 4;
            *(float4*)&S.Ks[r][c4] = *(const float4*)&K[kbase + (size_t)r * DH + c4];
            *(float4*)&S.Vs[r][c4] = *(const float4*)&V[kbase + (size_t)r * DH + c4];
        }
        __syncthreads();

        // S = Qs @ Ks^T  (64x64), 4x4 per thread
        float sacc[4][4];
#pragma unroll
        for (int i = 0; i < 4; i++)
#pragma unroll
            for (int j = 0; j < 4; j++) sacc[i][j] = 0.0f;

#pragma unroll 4
        for (int k4 = 0; k4 < 128; k4 += 4) {
            float4 qa[4], kb[4];
#pragma unroll
            for (int i = 0; i < 4; i++) qa[i] = *(const float4*)&S.Qs[sy*4 + i][k4];
#pragma unroll
            for (int j = 0; j < 4; j++) kb[j] = *(const float4*)&S.Ks[sx*4 + j][k4];
#pragma unroll
            for (int i = 0; i < 4; i++)
#pragma unroll
                for (int j = 0; j < 4; j++) {
                    sacc[i][j] = fmaf(qa[i].x, kb[j].x, sacc[i][j]);
                    sacc[i][j] = fmaf(qa[i].y, kb[j].y, sacc[i][j]);
                    sacc[i][j] = fmaf(qa[i].z, kb[j].z, sacc[i][j]);
                    sacc[i][j] = fmaf(qa[i].w, kb[j].w, sacc[i][j]);
                }
        }
        bool diag = (kt == qt);
#pragma unroll
        for (int i = 0; i < 4; i++)
#pragma unroll
            for (int j = 0; j < 4; j++) {
                float sv = sacc[i][j];
                if (diag && (sx*4 + j) > (sy*4 + i)) sv = -1e30f;
                S.Ss[sy*4 + i][sx*4 + j] = sv;
            }
        __syncthreads();

        // Online softmax, 4 threads per row
        {
            int r = tid >> 2, l4 = tid & 3;
            float mx = -1e30f;
            for (int c = l4; c < 64; c += 4) mx = fmaxf(mx, S.Ss[r][c]);
            mx = fmaxf(mx, __shfl_xor_sync(0xffffffffu, mx, 1));
            mx = fmaxf(mx, __shfl_xor_sync(0xffffffffu, mx, 2));
            float mold = S.mrow[r];
            float mnew = fmaxf(mold, mx);
            float sum = 0.0f;
            for (int c = l4; c < 64; c += 4) {
                float p = __expf(S.Ss[r][c] - mnew);
                S.Ss[r][c] = p;
                sum += p;
            }
            sum += __shfl_xor_sync(0xffffffffu, sum, 1);
            sum += __shfl_xor_sync(0xffffffffu, sum, 2);
            if (l4 == 0) {
                float fac = __expf(mold - mnew);
                S.frow[r] = fac;
                S.lrow[r] = S.lrow[r] * fac + sum;
                S.mrow[r] = mnew;
            }
        }
        __syncthreads();

        // O = O*fac + P @ V ; thread covers rows sy*4+i, cols sx*8+j
#pragma unroll
        for (int i = 0; i < 4; i++) {
            float fac = S.frow[sy*4 + i];
#pragma unroll
            for (int j = 0; j < 8; j++) accO[i][j] *= fac;
        }
#pragma unroll 4
        for (int kk = 0; kk < 64; kk++) {
            float p[4];
#pragma unroll
            for (int i = 0; i < 4; i++) p[i] = S.Ss[sy*4 + i][kk];
            float4 v0 = *(const float4*)&S.Vs[kk][sx*8];
            float4 v1 = *(const float4*)&S.Vs[kk][sx*8 + 4];
#pragma unroll
            for (int i = 0; i < 4; i++) {
                accO[i][0] = fmaf(p[i], v0.x, accO[i][0]);
                accO[i][1] = fmaf(p[i], v0.y, accO[i][1]);
                accO[i][2] = fmaf(p[i], v0.z, accO[i][2]);
                accO[i][3] = fmaf(p[i], v0.w, accO[i][3]);
                accO[i][4] = fmaf(p[i], v1.x, accO[i][4]);
                accO[i][5] = fmaf(p[i], v1.y, accO[i][5]);
                accO[i][6] = fmaf(p[i], v1.z, accO[i][6]);
                accO[i][7] = fmaf(p[i], v1.w, accO[i][7]);
            }
        }
        __syncthreads();
    }

    // Normalize and write in [B,T,D] layout
#pragma unroll
    for (int i = 0; i < 4; i++) {
        float inv = 1.0f / S.lrow[sy*4 + i];
        int t = qt * 64 + sy*4 + i;
        size_t off = ((size_t)(b * NT + t)) * ND + h * DH + sx * 8;
        float4 c0 = make_float4(accO[i][0]*inv, accO[i][1]*inv, accO[i][2]*inv, accO[i][3]*inv);
        float4 c1 = make_float4(accO[i][4]*inv, accO[i][5]*inv, accO[i][6]*inv, accO[i][7]*inv);
        *(float4*)&O[off]     = c0;
        *(float4*)&O[off + 4] = c1;
    }
}

// ---------------------------------------------------------------------------
extern "C" void kernel_launch(void* const* d_in, const int* in_sizes, int n_in,
                              void* d_out, int out_size)
{
    const float* x    = (const float*)d_in[0];
    const float* Wqkv = (const float*)d_in[1];
    const float* WO   = (const float*)d_in[2];
    float* out = (float*)d_out;

    float *qkv, *q, *k, *v, *att;
    cudaGetSymbolAddress((void**)&qkv, g_qkv);
    cudaGetSymbolAddress((void**)&q,   g_q);
    cudaGetSymbolAddress((void**)&k,   g_k);
    cudaGetSymbolAddress((void**)&v,   g_v);
    cudaGetSymbolAddress((void**)&att, g_att);

    // 1) QKV projection: [4096,2048] @ [6144,2048]^T -> [4096,6144]
    gemm_kn_kernel<<<dim3(3*ND/128, NM/128), 256>>>(x, Wqkv, qkv, NM, 3*ND, ND);

    // 2) RoPE + head split
    rope_split_kernel<<<(NB*NT*NH*64)/256, 256>>>(qkv, q, k, v);

    // 3) Causal flash attention
    size_t smem = sizeof(AttnSmem);
    cudaFuncSetAttribute(attn_kernel, cudaFuncAttributeMaxDynamicSharedMemorySize, (int)smem);
    attn_kernel<<<dim3(NT/64, NH, NB), 256, smem>>>(q, k, v, att);

    // 4) Output projection: [4096,2048] @ [2048,2048]^T -> [4096,2048]
    gemm_kn_kernel<<<dim3(ND/128, NM/128), 256>>>(att, WO, out, NM, ND, ND);
}

// round 6
// speedup vs baseline: 1.5624x; 1.5624x over previous
#include <cuda_runtime.h>
#include <math.h>
#include <stdint.h>

#define NB 2
#define NT 2048
#define ND 2048
#define NH 16
#define DH 128
#define NM (NB*NT)            // 4096 rows

// ---------------------------------------------------------------------------
// Scratch (static device globals: allowed; no cudaMalloc anywhere)
// ---------------------------------------------------------------------------
__device__ float g_qkv[(size_t)NM * 3 * ND];      // [M, 6144]
__device__ float g_q[(size_t)NB*NH*NT*DH];        // [B,H,T,Dh]
__device__ float g_k[(size_t)NB*NH*NT*DH];
__device__ float g_v[(size_t)NB*NH*NT*DH];
__device__ float g_att[(size_t)NM * ND];          // [B,T,D] attention output (tf32-rounded)
__device__ float g_xr[(size_t)NM * ND];           // tf32-rounded x
__device__ float g_wqkvr[(size_t)3 * ND * ND];    // tf32-rounded Wqkv
__device__ float g_wor[(size_t)ND * ND];          // tf32-rounded WO

// ---------------------------------------------------------------------------
// helpers
// ---------------------------------------------------------------------------
__device__ __forceinline__ uint32_t smem_u32(const void* p) {
    uint32_t a;
    asm("{ .reg .u64 t; cvta.to.shared.u64 t, %1; cvt.u32.u64 %0, t; }" : "=r"(a) : "l"(p));
    return a;
}
__device__ __forceinline__ float tf32r(float x) {
    uint32_t u;
    asm("cvt.rna.tf32.f32 %0, %1;" : "=r"(u) : "f"(x));
    return __uint_as_float(u);
}
__device__ __forceinline__ void cp_async16(uint32_t saddr, const void* gaddr) {
    asm volatile("cp.async.cg.shared.global [%0], [%1], 16;" :: "r"(saddr), "l"(gaddr) : "memory");
}
#define CP_COMMIT() asm volatile("cp.async.commit_group;" ::: "memory")
#define CP_WAIT(n)  asm volatile("cp.async.wait_group %0;" :: "n"(n) : "memory")

__device__ __forceinline__ void mma_tf32_m16n8k8(
    float& d0, float& d1, float& d2, float& d3,
    uint32_t a0, uint32_t a1, uint32_t a2, uint32_t a3,
    uint32_t b0, uint32_t b1)
{
    asm volatile(
        "mma.sync.aligned.m16n8k8.row.col.f32.tf32.tf32.f32 "
        "{%0,%1,%2,%3}, {%4,%5,%6,%7}, {%8,%9}, {%0,%1,%2,%3};"
        : "+f"(d0), "+f"(d1), "+f"(d2), "+f"(d3)
        : "r"(a0), "r"(a1), "r"(a2), "r"(a3), "r"(b0), "r"(b1));
}

// ---------------------------------------------------------------------------
// tf32 mma.sync GEMM: C[m,n] = sum_k A[m,k] * Bw[n,k], both K-major fp32
// (pre-rounded to tf32). CTA tile 128x128, 8 warps of 32(M)x64(N).
// 3-stage cp.async pipeline, K stage = 16.
// ---------------------------------------------------------------------------
#define GM 128
#define GN 128
#define GKS 16
#define STAGES 3
#define ROWP 20                               // padded row stride (floats)
#define HALF_SLOT (128 * ROWP)                // A or B tile, floats
#define SLOT (2 * HALF_SLOT)                  // per-stage floats
#define GEMM_SMEM (STAGES * SLOT * 4)         // 61440 bytes

__global__ __launch_bounds__(256)
void gemm_tc_kernel(const float* __restrict__ A, const float* __restrict__ Bw,
                    float* __restrict__ C, int M, int N, int K)
{
    extern __shared__ float smem[];
    const uint32_t smem_base = smem_u32(smem);
    const int tid  = threadIdx.x;
    const int wid  = tid >> 5;
    const int lane = tid & 31;
    const int grp  = lane >> 2;       // 0..7
    const int qid  = lane & 3;        // 0..3
    const int m0 = blockIdx.y * GM;
    const int n0 = blockIdx.x * GN;
    const int nk = K / GKS;

    const int wm = (wid & 3) * 32;    // warp M offset in tile
    const int wn = (wid >> 2) * 64;   // warp N offset in tile

    float d[2][8][4];
#pragma unroll
    for (int mi = 0; mi < 2; mi++)
#pragma unroll
        for (int ni = 0; ni < 8; ni++)
#pragma unroll
            for (int c = 0; c < 4; c++) d[mi][ni][c] = 0.0f;

    // each thread loads 2 float4 of A and 2 of B per stage
    const int lr  = tid >> 1;                 // 0..127 (row)
    const int lc0 = (tid & 1) * 2;            // chunk 0 or 2

    auto load_stage = [&](int s) {
        const int slot = s % STAGES;
        const int k0 = s * GKS;
        const uint32_t abase = smem_base + slot * SLOT * 4;
        const uint32_t bbase = abase + HALF_SLOT * 4;
#pragma unroll
        for (int c = 0; c < 2; c++) {
            uint32_t soff = (uint32_t)(lr * ROWP + (lc0 + c) * 4) * 4;
            cp_async16(abase + soff, &A [(size_t)(m0 + lr) * K + k0 + (lc0 + c) * 4]);
            cp_async16(bbase + soff, &Bw[(size_t)(n0 + lr) * K + k0 + (lc0 + c) * 4]);
        }
        CP_COMMIT();
    };

    load_stage(0);
    load_stage(1);

    for (int s = 0; s < nk; s++) {
        CP_WAIT(1);                 // stage s resident
        __syncthreads();            // all warps done computing stage s-1; data visible

        int ls = s + 2;
        if (ls < nk) load_stage(ls);

        const int slot = s % STAGES;
        const uint32_t* As = reinterpret_cast<const uint32_t*>(smem + slot * SLOT);
        const uint32_t* Bs = reinterpret_cast<const uint32_t*>(smem + slot * SLOT + HALF_SLOT);

#pragma unroll
        for (int kk = 0; kk < GKS; kk += 8) {
            uint32_t a[2][4], b[8][2];
#pragma unroll
            for (int mi = 0; mi < 2; mi++) {
                int r = wm + mi * 16 + grp;
                a[mi][0] = As[r * ROWP + kk + qid];
                a[mi][1] = As[(r + 8) * ROWP + kk + qid];
                a[mi][2] = As[r * ROWP + kk + qid + 4];
                a[mi][3] = As[(r + 8) * ROWP + kk + qid + 4];
            }
#pragma unroll
            for (int ni = 0; ni < 8; ni++) {
                int r = wn + ni * 8 + grp;
                b[ni][0] = Bs[r * ROWP + kk + qid];
                b[ni][1] = Bs[r * ROWP + kk + qid + 4];
            }
#pragma unroll
            for (int mi = 0; mi < 2; mi++)
#pragma unroll
                for (int ni = 0; ni < 8; ni++)
                    mma_tf32_m16n8k8(d[mi][ni][0], d[mi][ni][1], d[mi][ni][2], d[mi][ni][3],
                                     a[mi][0], a[mi][1], a[mi][2], a[mi][3],
                                     b[ni][0], b[ni][1]);
        }
    }

    // Epilogue: c0 at (row, col), c1 (row, col+1), c2 (row+8, col), c3 (row+8, col+1)
#pragma unroll
    for (int mi = 0; mi < 2; mi++) {
        int row = m0 + wm + mi * 16 + grp;
#pragma unroll
        for (int ni = 0; ni < 8; ni++) {
            int col = n0 + wn + ni * 8 + qid * 2;
            *(float2*)&C[(size_t)row * N + col]       = make_float2(d[mi][ni][0], d[mi][ni][1]);
            *(float2*)&C[(size_t)(row + 8) * N + col] = make_float2(d[mi][ni][2], d[mi][ni][3]);
        }
    }
}

// ---------------------------------------------------------------------------
// tf32 rna rounding (elementwise, float4)
// ---------------------------------------------------------------------------
__global__ __launch_bounds__(256)
void round_tf32_kernel(const float* __restrict__ in, float* __restrict__ out, int n4)
{
    int i = blockIdx.x * blockDim.x + threadIdx.x;
    if (i < n4) {
        float4 v = ((const float4*)in)[i];
        v.x = tf32r(v.x); v.y = tf32r(v.y); v.z = tf32r(v.z); v.w = tf32r(v.w);
        ((float4*)out)[i] = v;
    }
}

// ---------------------------------------------------------------------------
// RoPE + split into per-head layout [B,H,T,Dh]
// ---------------------------------------------------------------------------
__global__ __launch_bounds__(256)
void rope_split_kernel(const float* __restrict__ qkv,
                       float* __restrict__ q, float* __restrict__ k,
                       float* __restrict__ v)
{
    int idx = blockIdx.x * blockDim.x + threadIdx.x;    // 0 .. B*T*H*64-1
    int i = idx & 63;
    int h = (idx >> 6) & 15;
    int t = (idx >> 10) & 2047;
    int b = idx >> 21;

    int m = b * NT + t;
    const float* base = qkv + (size_t)m * (3 * ND);
    int col = h * DH + 2 * i;

    float q0 = base[col],          q1 = base[col + 1];
    float k0 = base[ND + col],     k1 = base[ND + col + 1];
    float v0 = base[2*ND + col],   v1 = base[2*ND + col + 1];

    float fr = expf(-logf(10000.0f) * (2.0f * (float)i) / (float)DH);
    float ang = (float)t * fr;
    float sn = sinf(ang), cs = cosf(ang);

    size_t o = ((size_t)(b * NH + h) * NT + t) * DH + 2 * i;
    q[o]     = q0 * cs - q1 * sn;
    q[o + 1] = q1 * cs + q0 * sn;
    k[o]     = k0 * cs - k1 * sn;
    k[o + 1] = k1 * cs + k0 * sn;
    v[o]     = v0;
    v[o + 1] = v1;
}

// ---------------------------------------------------------------------------
// Flash-style causal attention (fp32). Output tf32-rounded into [B,T,D].
// ---------------------------------------------------------------------------
struct AttnSmem {
    float Qs[64][132];
    float Ks[64][132];
    float Vs[64][132];
    float Ss[64][68];
    float mrow[64];
    float lrow[64];
    float frow[64];
};

__global__ __launch_bounds__(256)
void attn_kernel(const float* __restrict__ Q, const float* __restrict__ K,
                 const float* __restrict__ V, float* __restrict__ O)
{
    extern __shared__ unsigned char smem_bytes[];
    AttnSmem& S = *reinterpret_cast<AttnSmem*>(smem_bytes);

    const int tid = threadIdx.x;
    const int qt = blockIdx.x;      // query tile
    const int h  = blockIdx.y;
    const int b  = blockIdx.z;

    const float scale = 0.08838834764831845f;   // 1/sqrt(128)
    const size_t head_base = (size_t)(b * NH + h) * NT * DH;

    {
        size_t qbase = head_base + (size_t)qt * 64 * DH;
#pragma unroll
        for (int u = 0; u < 8; u++) {
            int e = tid + u * 256;
            int r = e >> 5;
            int c4 = (e & 31) * 4;
            float4 qv = *(const float4*)&Q[qbase + (size_t)r * DH + c4];
            qv.x *= scale; qv.y *= scale; qv.z *= scale; qv.w *= scale;
            *(float4*)&S.Qs[r][c4] = qv;
        }
    }
    if (tid < 64) { S.mrow[tid] = -1e30f; S.lrow[tid] = 0.0f; S.frow[tid] = 0.0f; }

    const int sy = tid >> 4, sx = tid & 15;
    float accO[4][8];
#pragma unroll
    for (int i = 0; i < 4; i++)
#pragma unroll
        for (int j = 0; j < 8; j++) accO[i][j] = 0.0f;

    for (int kt = 0; kt <= qt; kt++) {
        size_t kbase = head_base + (size_t)kt * 64 * DH;
#pragma unroll
        for (int u = 0; u < 8; u++) {
            int e = tid + u * 256;
            int r = e >> 5;
            int c4 = (e & 31) * 4;
            *(float4*)&S.Ks[r][c4] = *(const float4*)&K[kbase + (size_t)r * DH + c4];
            *(float4*)&S.Vs[r][c4] = *(const float4*)&V[kbase + (size_t)r * DH + c4];
        }
        __syncthreads();

        float sacc[4][4];
#pragma unroll
        for (int i = 0; i < 4; i++)
#pragma unroll
            for (int j = 0; j < 4; j++) sacc[i][j] = 0.0f;

#pragma unroll 4
        for (int k4 = 0; k4 < 128; k4 += 4) {
            float4 qa[4], kb[4];
#pragma unroll
            for (int i = 0; i < 4; i++) qa[i] = *(const float4*)&S.Qs[sy*4 + i][k4];
#pragma unroll
            for (int j = 0; j < 4; j++) kb[j] = *(const float4*)&S.Ks[sx*4 + j][k4];
#pragma unroll
            for (int i = 0; i < 4; i++)
#pragma unroll
                for (int j = 0; j < 4; j++) {
                    sacc[i][j] = fmaf(qa[i].x, kb[j].x, sacc[i][j]);
                    sacc[i][j] = fmaf(qa[i].y, kb[j].y, sacc[i][j]);
                    sacc[i][j] = fmaf(qa[i].z, kb[j].z, sacc[i][j]);
                    sacc[i][j] = fmaf(qa[i].w, kb[j].w, sacc[i][j]);
                }
        }
        bool diag = (kt == qt);
#pragma unroll
        for (int i = 0; i < 4; i++)
#pragma unroll
            for (int j = 0; j < 4; j++) {
                float sv = sacc[i][j];
                if (diag && (sx*4 + j) > (sy*4 + i)) sv = -1e30f;
                S.Ss[sy*4 + i][sx*4 + j] = sv;
            }
        __syncthreads();

        {
            int r = tid >> 2, l4 = tid & 3;
            float mx = -1e30f;
            for (int c = l4; c < 64; c += 4) mx = fmaxf(mx, S.Ss[r][c]);
            mx = fmaxf(mx, __shfl_xor_sync(0xffffffffu, mx, 1));
            mx = fmaxf(mx, __shfl_xor_sync(0xffffffffu, mx, 2));
            float mold = S.mrow[r];
            float mnew = fmaxf(mold, mx);
            float sum = 0.0f;
            for (int c = l4; c < 64; c += 4) {
                float p = __expf(S.Ss[r][c] - mnew);
                S.Ss[r][c] = p;
                sum += p;
            }
            sum += __shfl_xor_sync(0xffffffffu, sum, 1);
            sum += __shfl_xor_sync(0xffffffffu, sum, 2);
            if (l4 == 0) {
                float fac = __expf(mold - mnew);
                S.frow[r] = fac;
                S.lrow[r] = S.lrow[r] * fac + sum;
                S.mrow[r] = mnew;
            }
        }
        __syncthreads();

#pragma unroll
        for (int i = 0; i < 4; i++) {
            float fac = S.frow[sy*4 + i];
#pragma unroll
            for (int j = 0; j < 8; j++) accO[i][j] *= fac;
        }
#pragma unroll 4
        for (int kk = 0; kk < 64; kk++) {
            float p[4];
#pragma unroll
            for (int i = 0; i < 4; i++) p[i] = S.Ss[sy*4 + i][kk];
            float4 v0 = *(const float4*)&S.Vs[kk][sx*8];
            float4 v1 = *(const float4*)&S.Vs[kk][sx*8 + 4];
#pragma unroll
            for (int i = 0; i < 4; i++) {
                accO[i][0] = fmaf(p[i], v0.x, accO[i][0]);
                accO[i][1] = fmaf(p[i], v0.y, accO[i][1]);
                accO[i][2] = fmaf(p[i], v0.z, accO[i][2]);
                accO[i][3] = fmaf(p[i], v0.w, accO[i][3]);
                accO[i][4] = fmaf(p[i], v1.x, accO[i][4]);
                accO[i][5] = fmaf(p[i], v1.y, accO[i][5]);
                accO[i][6] = fmaf(p[i], v1.z, accO[i][6]);
                accO[i][7] = fmaf(p[i], v1.w, accO[i][7]);
            }
        }
        __syncthreads();
    }

    // Normalize + tf32 round + write in [B,T,D] layout (feeds tf32 GEMM2)
#pragma unroll
    for (int i = 0; i < 4; i++) {
        float inv = 1.0f / S.lrow[sy*4 + i];
        int t = qt * 64 + sy*4 + i;
        size_t off = ((size_t)(b * NT + t)) * ND + h * DH + sx * 8;
        float4 c0 = make_float4(tf32r(accO[i][0]*inv), tf32r(accO[i][1]*inv),
                                tf32r(accO[i][2]*inv), tf32r(accO[i][3]*inv));
        float4 c1 = make_float4(tf32r(accO[i][4]*inv), tf32r(accO[i][5]*inv),
                                tf32r(accO[i][6]*inv), tf32r(accO[i][7]*inv));
        *(float4*)&O[off]     = c0;
        *(float4*)&O[off + 4] = c1;
    }
}

// ---------------------------------------------------------------------------
extern "C" void kernel_launch(void* const* d_in, const int* in_sizes, int n_in,
                              void* d_out, int out_size)
{
    const float* x    = (const float*)d_in[0];
    const float* Wqkv = (const float*)d_in[1];
    const float* WO   = (const float*)d_in[2];
    float* out = (float*)d_out;

    float *qkv, *q, *k, *v, *att, *xr, *wr, *wor;
    cudaGetSymbolAddress((void**)&qkv, g_qkv);
    cudaGetSymbolAddress((void**)&q,   g_q);
    cudaGetSymbolAddress((void**)&k,   g_k);
    cudaGetSymbolAddress((void**)&v,   g_v);
    cudaGetSymbolAddress((void**)&att, g_att);
    cudaGetSymbolAddress((void**)&xr,  g_xr);
    cudaGetSymbolAddress((void**)&wr,  g_wqkvr);
    cudaGetSymbolAddress((void**)&wor, g_wor);

    // 0) tf32-round GEMM operands (unbiased rna)
    round_tf32_kernel<<<(NM*ND/4)/256, 256>>>(x, xr, NM*ND/4);
    round_tf32_kernel<<<(3*ND*ND/4)/256, 256>>>(Wqkv, wr, 3*ND*ND/4);
    round_tf32_kernel<<<(ND*ND/4)/256, 256>>>(WO, wor, ND*ND/4);

    // 1) QKV projection, tf32 mma.sync: [4096,2048] @ [6144,2048]^T -> [4096,6144]
    cudaFuncSetAttribute(gemm_tc_kernel, cudaFuncAttributeMaxDynamicSharedMemorySize, GEMM_SMEM);
    gemm_tc_kernel<<<dim3(3*ND/GN, NM/GM), 256, GEMM_SMEM>>>(xr, wr, qkv, NM, 3*ND, ND);

    // 2) RoPE + head split
    rope_split_kernel<<<(NB*NT*NH*64)/256, 256>>>(qkv, q, k, v);

    // 3) Causal flash attention
    size_t smem = sizeof(AttnSmem);
    cudaFuncSetAttribute(attn_kernel, cudaFuncAttributeMaxDynamicSharedMemorySize, (int)smem);
    attn_kernel<<<dim3(NT/64, NH, NB), 256, smem>>>(q, k, v, att);

    // 4) Output projection, tf32 mma.sync: [4096,2048] @ [2048,2048]^T -> [4096,2048]
    gemm_tc_kernel<<<dim3(ND/GN, NM/GM), 256, GEMM_SMEM>>>(att, wor, out, NM, ND, ND);
}

// round 8
// speedup vs baseline: 3.2422x; 2.0752x over previous
#include <cuda_runtime.h>
#include <math.h>
#include <stdint.h>

#define NB 2
#define NT 2048
#define ND 2048
#define NH 16
#define DH 128
#define NM (NB*NT)            // 4096 rows

// ---------------------------------------------------------------------------
// Scratch (static device globals: allowed; no cudaMalloc anywhere)
// ---------------------------------------------------------------------------
__device__ float g_qkv[(size_t)NM * 3 * ND];      // [M, 6144]
__device__ float g_q[(size_t)NB*NH*NT*DH];        // [B,H,T,Dh]  (tf32, pre-scaled)
__device__ float g_k[(size_t)NB*NH*NT*DH];        // tf32
__device__ float g_v[(size_t)NB*NH*NT*DH];        // tf32
__device__ float g_att[(size_t)NM * ND];          // [B,T,D] attention output (tf32)
__device__ float g_xr[(size_t)NM * ND];           // tf32-rounded x
__device__ float g_wqkvr[(size_t)3 * ND * ND];    // tf32-rounded Wqkv
__device__ float g_wor[(size_t)ND * ND];          // tf32-rounded WO

// ---------------------------------------------------------------------------
// helpers
// ---------------------------------------------------------------------------
__device__ __forceinline__ uint32_t smem_u32(const void* p) {
    uint32_t a;
    asm("{ .reg .u64 t; cvta.to.shared.u64 t, %1; cvt.u32.u64 %0, t; }" : "=r"(a) : "l"(p));
    return a;
}
__device__ __forceinline__ float tf32r(float x) {
    uint32_t u;
    asm("cvt.rna.tf32.f32 %0, %1;" : "=r"(u) : "f"(x));
    return __uint_as_float(u);
}
__device__ __forceinline__ void cp_async16(uint32_t saddr, const void* gaddr) {
    asm volatile("cp.async.cg.shared.global [%0], [%1], 16;" :: "r"(saddr), "l"(gaddr) : "memory");
}
#define CP_COMMIT() asm volatile("cp.async.commit_group;" ::: "memory")
#define CP_WAIT(n)  asm volatile("cp.async.wait_group %0;" :: "n"(n) : "memory")

__device__ __forceinline__ void mma_tf32_m16n8k8(
    float& d0, float& d1, float& d2, float& d3,
    uint32_t a0, uint32_t a1, uint32_t a2, uint32_t a3,
    uint32_t b0, uint32_t b1)
{
    asm volatile(
        "mma.sync.aligned.m16n8k8.row.col.f32.tf32.tf32.f32 "
        "{%0,%1,%2,%3}, {%4,%5,%6,%7}, {%8,%9}, {%0,%1,%2,%3};"
        : "+f"(d0), "+f"(d1), "+f"(d2), "+f"(d3)
        : "r"(a0), "r"(a1), "r"(a2), "r"(a3), "r"(b0), "r"(b1));
}

// ---------------------------------------------------------------------------
// tf32 mma.sync GEMM: C[m,n] = sum_k A[m,k] * Bw[n,k]  (unchanged from R6)
// ---------------------------------------------------------------------------
#define GM 128
#define GN 128
#define GKS 16
#define STAGES 3
#define ROWP 20
#define HALF_SLOT (128 * ROWP)
#define SLOT (2 * HALF_SLOT)
#define GEMM_SMEM (STAGES * SLOT * 4)

__global__ __launch_bounds__(256)
void gemm_tc_kernel(const float* __restrict__ A, const float* __restrict__ Bw,
                    float* __restrict__ C, int M, int N, int K)
{
    extern __shared__ float smem[];
    const uint32_t smem_base = smem_u32(smem);
    const int tid  = threadIdx.x;
    const int wid  = tid >> 5;
    const int lane = tid & 31;
    const int grp  = lane >> 2;
    const int qid  = lane & 3;
    const int m0 = blockIdx.y * GM;
    const int n0 = blockIdx.x * GN;
    const int nk = K / GKS;

    const int wm = (wid & 3) * 32;
    const int wn = (wid >> 2) * 64;

    float d[2][8][4];
#pragma unroll
    for (int mi = 0; mi < 2; mi++)
#pragma unroll
        for (int ni = 0; ni < 8; ni++)
#pragma unroll
            for (int c = 0; c < 4; c++) d[mi][ni][c] = 0.0f;

    const int lr  = tid >> 1;
    const int lc0 = (tid & 1) * 2;

    auto load_stage = [&](int s) {
        const int slot = s % STAGES;
        const int k0 = s * GKS;
        const uint32_t abase = smem_base + slot * SLOT * 4;
        const uint32_t bbase = abase + HALF_SLOT * 4;
#pragma unroll
        for (int c = 0; c < 2; c++) {
            uint32_t soff = (uint32_t)(lr * ROWP + (lc0 + c) * 4) * 4;
            cp_async16(abase + soff, &A [(size_t)(m0 + lr) * K + k0 + (lc0 + c) * 4]);
            cp_async16(bbase + soff, &Bw[(size_t)(n0 + lr) * K + k0 + (lc0 + c) * 4]);
        }
        CP_COMMIT();
    };

    load_stage(0);
    load_stage(1);

    for (int s = 0; s < nk; s++) {
        CP_WAIT(1);
        __syncthreads();

        int ls = s + 2;
        if (ls < nk) load_stage(ls);

        const int slot = s % STAGES;
        const uint32_t* As = reinterpret_cast<const uint32_t*>(smem + slot * SLOT);
        const uint32_t* Bs = reinterpret_cast<const uint32_t*>(smem + slot * SLOT + HALF_SLOT);

#pragma unroll
        for (int kk = 0; kk < GKS; kk += 8) {
            uint32_t a[2][4], b[8][2];
#pragma unroll
            for (int mi = 0; mi < 2; mi++) {
                int r = wm + mi * 16 + grp;
                a[mi][0] = As[r * ROWP + kk + qid];
                a[mi][1] = As[(r + 8) * ROWP + kk + qid];
                a[mi][2] = As[r * ROWP + kk + qid + 4];
                a[mi][3] = As[(r + 8) * ROWP + kk + qid + 4];
            }
#pragma unroll
            for (int ni = 0; ni < 8; ni++) {
                int r = wn + ni * 8 + grp;
                b[ni][0] = Bs[r * ROWP + kk + qid];
                b[ni][1] = Bs[r * ROWP + kk + qid + 4];
            }
#pragma unroll
            for (int mi = 0; mi < 2; mi++)
#pragma unroll
                for (int ni = 0; ni < 8; ni++)
                    mma_tf32_m16n8k8(d[mi][ni][0], d[mi][ni][1], d[mi][ni][2], d[mi][ni][3],
                                     a[mi][0], a[mi][1], a[mi][2], a[mi][3],
                                     b[ni][0], b[ni][1]);
        }
    }

#pragma unroll
    for (int mi = 0; mi < 2; mi++) {
        int row = m0 + wm + mi * 16 + grp;
#pragma unroll
        for (int ni = 0; ni < 8; ni++) {
            int col = n0 + wn + ni * 8 + qid * 2;
            *(float2*)&C[(size_t)row * N + col]       = make_float2(d[mi][ni][0], d[mi][ni][1]);
            *(float2*)&C[(size_t)(row + 8) * N + col] = make_float2(d[mi][ni][2], d[mi][ni][3]);
        }
    }
}

// ---------------------------------------------------------------------------
// tf32 rna rounding (elementwise, float4)
// ---------------------------------------------------------------------------
__global__ __launch_bounds__(256)
void round_tf32_kernel(const float* __restrict__ in, float* __restrict__ out, int n4)
{
    int i = blockIdx.x * blockDim.x + threadIdx.x;
    if (i < n4) {
        float4 v = ((const float4*)in)[i];
        v.x = tf32r(v.x); v.y = tf32r(v.y); v.z = tf32r(v.z); v.w = tf32r(v.w);
        ((float4*)out)[i] = v;
    }
}

// ---------------------------------------------------------------------------
// RoPE + head split; outputs tf32-rounded; q pre-scaled by 1/sqrt(Dh)
// ---------------------------------------------------------------------------
__global__ __launch_bounds__(256)
void rope_split_kernel(const float* __restrict__ qkv,
                       float* __restrict__ q, float* __restrict__ k,
                       float* __restrict__ v)
{
    int idx = blockIdx.x * blockDim.x + threadIdx.x;
    int i = idx & 63;
    int h = (idx >> 6) & 15;
    int t = (idx >> 10) & 2047;
    int b = idx >> 21;

    int m = b * NT + t;
    const float* base = qkv + (size_t)m * (3 * ND);
    int col = h * DH + 2 * i;

    float q0 = base[col],          q1 = base[col + 1];
    float k0 = base[ND + col],     k1 = base[ND + col + 1];
    float v0 = base[2*ND + col],   v1 = base[2*ND + col + 1];

    float fr = expf(-logf(10000.0f) * (2.0f * (float)i) / (float)DH);
    float ang = (float)t * fr;
    float sn = sinf(ang), cs = cosf(ang);
    const float scale = 0.08838834764831845f;   // 1/sqrt(128)

    size_t o = ((size_t)(b * NH + h) * NT + t) * DH + 2 * i;
    q[o]     = tf32r((q0 * cs - q1 * sn) * scale);
    q[o + 1] = tf32r((q1 * cs + q0 * sn) * scale);
    k[o]     = tf32r(k0 * cs - k1 * sn);
    k[o + 1] = tf32r(k1 * cs + k0 * sn);
    v[o]     = tf32r(v0);
    v[o + 1] = tf32r(v1);
}

// ---------------------------------------------------------------------------
// Tensor-core causal flash attention (tf32 mma.sync).
// Block: 64 q-rows, 8 warps = 4 M-slices x 2 N-halves. K/V tiles of 64 keys,
// double-buffered cp.async. Softmax in registers (quad shuffles + smem
// partials across the two N-half warps). P via smem for the PV mma.
// ---------------------------------------------------------------------------
#define AQ 64
#define AK 64
#define QPAD 140
#define KPAD 140
#define VPAD 136
#define PPAD 76

// smem layout in floats
#define QS_OFF 0                         // 64*140 = 8960
#define KS_OFF 8960                      // 2 x 8960
#define VS_OFF 26880                     // 2 x 8704
#define PS_OFF 44288                     // 64*76 = 4864
#define PM_OFF 49152                     // pmax[64][2]
#define PL_OFF 49280                     // psum[64][2]
#define ATTN_FLOATS 49408
#define ATTN_SMEM (ATTN_FLOATS * 4)      // 197632 bytes

__global__ __launch_bounds__(256, 1)
void attn_tc_kernel(const float* __restrict__ Q, const float* __restrict__ K,
                    const float* __restrict__ V, float* __restrict__ O)
{
    extern __shared__ float sm[];
    const uint32_t smem_base = smem_u32(sm);
    uint32_t* smU = reinterpret_cast<uint32_t*>(sm);

    const int tid  = threadIdx.x;
    const int wid  = tid >> 5;
    const int lane = tid & 31;
    const int grp  = lane >> 2;       // 0..7
    const int qid  = lane & 3;        // 0..3
    const int ws   = wid & 3;         // M slice (16 rows)
    const int wn   = wid >> 2;        // N half

    const int qt = blockIdx.x;
    const int h  = blockIdx.y;
    const int b  = blockIdx.z;
    const size_t head_base = (size_t)(b * NH + h) * NT * DH;

    // ---- load Q tile (64 x 128) into smem ----
    {
        const float* qb = Q + head_base + (size_t)qt * AQ * DH;
#pragma unroll
        for (int u = 0; u < 8; u++) {
            int e = tid + u * 256;
            int r = e >> 5;
            int c4 = (e & 31) * 4;
            *(float4*)&sm[QS_OFF + r * QPAD + c4] = *(const float4*)&qb[(size_t)r * DH + c4];
        }
    }

    // ---- prologue: K/V tile 0 ----
    auto load_kv = [&](int tile, int buf) {
        const float* kb = K + head_base + (size_t)tile * AK * DH;
        const float* vb = V + head_base + (size_t)tile * AK * DH;
#pragma unroll
        for (int u = 0; u < 8; u++) {
            int e = tid + u * 256;
            int r = e >> 5;
            int c4 = (e & 31) * 4;
            cp_async16(smem_base + (uint32_t)(KS_OFF + buf * (AK*KPAD) + r * KPAD + c4) * 4,
                       &kb[(size_t)r * DH + c4]);
            cp_async16(smem_base + (uint32_t)(VS_OFF + buf * (AK*VPAD) + r * VPAD + c4) * 4,
                       &vb[(size_t)r * DH + c4]);
        }
        CP_COMMIT();
    };
    load_kv(0, 0);
    __syncthreads();                 // Q visible

    // ---- cache Q fragments in registers: 16 k8-steps x 4 regs ----
    const int row0 = ws * 16 + grp;  // local q row
    const int row1 = row0 + 8;
    uint32_t Qf[16][4];
#pragma unroll
    for (int s = 0; s < 16; s++) {
        int c = s * 8 + qid;
        Qf[s][0] = smU[QS_OFF + row0 * QPAD + c];
        Qf[s][1] = smU[QS_OFF + row1 * QPAD + c];
        Qf[s][2] = smU[QS_OFF + row0 * QPAD + c + 4];
        Qf[s][3] = smU[QS_OFF + row1 * QPAD + c + 4];
    }

    float accO[8][4];
#pragma unroll
    for (int ni = 0; ni < 8; ni++)
#pragma unroll
        for (int c = 0; c < 4; c++) accO[ni][c] = 0.0f;
    float m0 = -1e30f, m1 = -1e30f, l0 = 0.0f, l1 = 0.0f;

    for (int kt = 0; kt <= qt; kt++) {
        const int buf = kt & 1;
        if (kt < qt) { load_kv(kt + 1, buf ^ 1); CP_WAIT(1); }
        else         { CP_WAIT(0); }
        __syncthreads();             // K/V tile kt resident for all threads

        // ---- S = Q K^T  (rows row0/row1, cols wn*32 + ni*8 + 2qid(+1)) ----
        float sa[4][4];
#pragma unroll
        for (int ni = 0; ni < 4; ni++)
#pragma unroll
            for (int c = 0; c < 4; c++) sa[ni][c] = 0.0f;

        const uint32_t* Ks = smU + KS_OFF + buf * (AK*KPAD);
#pragma unroll
        for (int s = 0; s < 16; s++) {
            int kk = s * 8;
            uint32_t b0[4], b1[4];
#pragma unroll
            for (int ni = 0; ni < 4; ni++) {
                int kr = wn * 32 + ni * 8 + grp;
                b0[ni] = Ks[kr * KPAD + kk + qid];
                b1[ni] = Ks[kr * KPAD + kk + qid + 4];
            }
#pragma unroll
            for (int ni = 0; ni < 4; ni++)
                mma_tf32_m16n8k8(sa[ni][0], sa[ni][1], sa[ni][2], sa[ni][3],
                                 Qf[s][0], Qf[s][1], Qf[s][2], Qf[s][3],
                                 b0[ni], b1[ni]);
        }

        // ---- causal mask on diagonal tile ----
        if (kt == qt) {
#pragma unroll
            for (int ni = 0; ni < 4; ni++) {
                int cl = wn * 32 + ni * 8 + 2 * qid;
                if (cl     > row0) sa[ni][0] = -1e30f;
                if (cl + 1 > row0) sa[ni][1] = -1e30f;
                if (cl     > row1) sa[ni][2] = -1e30f;
                if (cl + 1 > row1) sa[ni][3] = -1e30f;
            }
        }

        // ---- partial row max over this thread's 8 cols/row, quad-reduce ----
        float pm0 = -1e30f, pm1 = -1e30f;
#pragma unroll
        for (int ni = 0; ni < 4; ni++) {
            pm0 = fmaxf(pm0, fmaxf(sa[ni][0], sa[ni][1]));
            pm1 = fmaxf(pm1, fmaxf(sa[ni][2], sa[ni][3]));
        }
        pm0 = fmaxf(pm0, __shfl_xor_sync(0xffffffffu, pm0, 1));
        pm0 = fmaxf(pm0, __shfl_xor_sync(0xffffffffu, pm0, 2));
        pm1 = fmaxf(pm1, __shfl_xor_sync(0xffffffffu, pm1, 1));
        pm1 = fmaxf(pm1, __shfl_xor_sync(0xffffffffu, pm1, 2));
        if (qid == 0) {
            sm[PM_OFF + row0 * 2 + wn] = pm0;
            sm[PM_OFF + row1 * 2 + wn] = pm1;
        }
        __syncthreads();

        float mn0 = fmaxf(m0, fmaxf(sm[PM_OFF + row0 * 2], sm[PM_OFF + row0 * 2 + 1]));
        float mn1 = fmaxf(m1, fmaxf(sm[PM_OFF + row1 * 2], sm[PM_OFF + row1 * 2 + 1]));

        // ---- P = exp(S - m), partial sums, store P (tf32) to smem ----
        float ps0 = 0.0f, ps1 = 0.0f;
#pragma unroll
        for (int ni = 0; ni < 4; ni++) {
            float p00 = __expf(sa[ni][0] - mn0);
            float p01 = __expf(sa[ni][1] - mn0);
            float p10 = __expf(sa[ni][2] - mn1);
            float p11 = __expf(sa[ni][3] - mn1);
            ps0 += p00 + p01;
            ps1 += p10 + p11;
            int cl = wn * 32 + ni * 8 + 2 * qid;
            *(float2*)&sm[PS_OFF + row0 * PPAD + cl] = make_float2(tf32r(p00), tf32r(p01));
            *(float2*)&sm[PS_OFF + row1 * PPAD + cl] = make_float2(tf32r(p10), tf32r(p11));
        }
        ps0 += __shfl_xor_sync(0xffffffffu, ps0, 1);
        ps0 += __shfl_xor_sync(0xffffffffu, ps0, 2);
        ps1 += __shfl_xor_sync(0xffffffffu, ps1, 1);
        ps1 += __shfl_xor_sync(0xffffffffu, ps1, 2);
        if (qid == 0) {
            sm[PL_OFF + row0 * 2 + wn] = ps0;
            sm[PL_OFF + row1 * 2 + wn] = ps1;
        }
        __syncthreads();

        float fac0 = __expf(m0 - mn0);
        float fac1 = __expf(m1 - mn1);
        m0 = mn0; m1 = mn1;
        l0 = l0 * fac0 + sm[PL_OFF + row0 * 2] + sm[PL_OFF + row0 * 2 + 1];
        l1 = l1 * fac1 + sm[PL_OFF + row1 * 2] + sm[PL_OFF + row1 * 2 + 1];

#pragma unroll
        for (int ni = 0; ni < 8; ni++) {
            accO[ni][0] *= fac0; accO[ni][1] *= fac0;
            accO[ni][2] *= fac1; accO[ni][3] *= fac1;
        }

        // ---- O += P V  (cols wn*64 + ni*8 + 2qid(+1)) ----
        const uint32_t* Vs = smU + VS_OFF + buf * (AK*VPAD);
#pragma unroll
        for (int s8 = 0; s8 < 8; s8++) {
            int kk = s8 * 8;
            uint32_t a0 = smU[PS_OFF + row0 * PPAD + kk + qid];
            uint32_t a1 = smU[PS_OFF + row1 * PPAD + kk + qid];
            uint32_t a2 = smU[PS_OFF + row0 * PPAD + kk + qid + 4];
            uint32_t a3 = smU[PS_OFF + row1 * PPAD + kk + qid + 4];
#pragma unroll
            for (int ni = 0; ni < 8; ni++) {
                int vc = wn * 64 + ni * 8 + grp;
                uint32_t b0 = Vs[(kk + qid) * VPAD + vc];
                uint32_t b1 = Vs[(kk + qid + 4) * VPAD + vc];
                mma_tf32_m16n8k8(accO[ni][0], accO[ni][1], accO[ni][2], accO[ni][3],
                                 a0, a1, a2, a3, b0, b1);
            }
        }
        __syncthreads();             // protect Ps & K/V buffers before next iter
    }

    // ---- normalize and write [B,T,D] (tf32-rounded for GEMM2) ----
    float inv0 = 1.0f / l0, inv1 = 1.0f / l1;
    int t0 = qt * AQ + row0;
    int t1 = qt * AQ + row1;
#pragma unroll
    for (int ni = 0; ni < 8; ni++) {
        int col = h * DH + wn * 64 + ni * 8 + 2 * qid;
        *(float2*)&O[(size_t)(b * NT + t0) * ND + col] =
            make_float2(tf32r(accO[ni][0] * inv0), tf32r(accO[ni][1] * inv0));
        *(float2*)&O[(size_t)(b * NT + t1) * ND + col] =
            make_float2(tf32r(accO[ni][2] * inv1), tf32r(accO[ni][3] * inv1));
    }
}

// ---------------------------------------------------------------------------
extern "C" void kernel_launch(void* const* d_in, const int* in_sizes, int n_in,
                              void* d_out, int out_size)
{
    const float* x    = (const float*)d_in[0];
    const float* Wqkv = (const float*)d_in[1];
    const float* WO   = (const float*)d_in[2];
    float* out = (float*)d_out;

    float *qkv, *q, *k, *v, *att, *xr, *wr, *wor;
    cudaGetSymbolAddress((void**)&qkv, g_qkv);
    cudaGetSymbolAddress((void**)&q,   g_q);
    cudaGetSymbolAddress((void**)&k,   g_k);
    cudaGetSymbolAddress((void**)&v,   g_v);
    cudaGetSymbolAddress((void**)&att, g_att);
    cudaGetSymbolAddress((void**)&xr,  g_xr);
    cudaGetSymbolAddress((void**)&wr,  g_wqkvr);
    cudaGetSymbolAddress((void**)&wor, g_wor);

    // 0) tf32-round GEMM operands
    round_tf32_kernel<<<(NM*ND/4)/256, 256>>>(x, xr, NM*ND/4);
    round_tf32_kernel<<<(3*ND*ND/4)/256, 256>>>(Wqkv, wr, 3*ND*ND/4);
    round_tf32_kernel<<<(ND*ND/4)/256, 256>>>(WO, wor, ND*ND/4);

    // 1) QKV projection (tf32 mma.sync)
    cudaFuncSetAttribute(gemm_tc_kernel, cudaFuncAttributeMaxDynamicSharedMemorySize, GEMM_SMEM);
    gemm_tc_kernel<<<dim3(3*ND/GN, NM/GM), 256, GEMM_SMEM>>>(xr, wr, qkv, NM, 3*ND, ND);

    // 2) RoPE + head split (tf32 outputs, q pre-scaled)
    rope_split_kernel<<<(NB*NT*NH*64)/256, 256>>>(qkv, q, k, v);

    // 3) Tensor-core causal flash attention
    cudaFuncSetAttribute(attn_tc_kernel, cudaFuncAttributeMaxDynamicSharedMemorySize, ATTN_SMEM);
    attn_tc_kernel<<<dim3(NT/AQ, NH, NB), 256, ATTN_SMEM>>>(q, k, v, att);

    // 4) Output projection (tf32 mma.sync)
    gemm_tc_kernel<<<dim3(ND/GN, NM/GM), 256, GEMM_SMEM>>>(att, wor, out, NM, ND, ND);
}

// round 9
// speedup vs baseline: 3.5355x; 1.0905x over previous
#include <cuda_runtime.h>
#include <math.h>
#include <stdint.h>

#define NB 2
#define NT 2048
#define ND 2048
#define NH 16
#define DH 128
#define NM (NB*NT)            // 4096 rows

// ---------------------------------------------------------------------------
// Scratch (static device globals: allowed; no cudaMalloc anywhere)
// ---------------------------------------------------------------------------
__device__ float g_qkv[(size_t)NM * 3 * ND];      // [M, 6144]
__device__ float g_q[(size_t)NB*NH*NT*DH];        // [B,H,T,Dh]  (tf32, pre-scaled)
__device__ float g_k[(size_t)NB*NH*NT*DH];        // tf32
__device__ float g_v[(size_t)NB*NH*NT*DH];        // tf32
__device__ float g_att[(size_t)NM * ND];          // [B,T,D] attention output (tf32)
__device__ float g_xr[(size_t)NM * ND];           // tf32-rounded x
__device__ float g_wqkvr[(size_t)3 * ND * ND];    // tf32-rounded Wqkv
__device__ float g_wor[(size_t)ND * ND];          // tf32-rounded WO

// ---------------------------------------------------------------------------
// helpers
// ---------------------------------------------------------------------------
__device__ __forceinline__ uint32_t smem_u32(const void* p) {
    uint32_t a;
    asm("{ .reg .u64 t; cvta.to.shared.u64 t, %1; cvt.u32.u64 %0, t; }" : "=r"(a) : "l"(p));
    return a;
}
__device__ __forceinline__ float tf32r(float x) {
    uint32_t u;
    asm("cvt.rna.tf32.f32 %0, %1;" : "=r"(u) : "f"(x));
    return __uint_as_float(u);
}
__device__ __forceinline__ void cp_async16(uint32_t saddr, const void* gaddr) {
    asm volatile("cp.async.cg.shared.global [%0], [%1], 16;" :: "r"(saddr), "l"(gaddr) : "memory");
}
#define CP_COMMIT() asm volatile("cp.async.commit_group;" ::: "memory")
#define CP_WAIT(n)  asm volatile("cp.async.wait_group %0;" :: "n"(n) : "memory")

__device__ __forceinline__ void mma_tf32_m16n8k8(
    float& d0, float& d1, float& d2, float& d3,
    uint32_t a0, uint32_t a1, uint32_t a2, uint32_t a3,
    uint32_t b0, uint32_t b1)
{
    asm volatile(
        "mma.sync.aligned.m16n8k8.row.col.f32.tf32.tf32.f32 "
        "{%0,%1,%2,%3}, {%4,%5,%6,%7}, {%8,%9}, {%0,%1,%2,%3};"
        : "+f"(d0), "+f"(d1), "+f"(d2), "+f"(d3)
        : "r"(a0), "r"(a1), "r"(a2), "r"(a3), "r"(b0), "r"(b1));
}
__device__ __forceinline__ void ldsm_x4(uint32_t& r0, uint32_t& r1, uint32_t& r2, uint32_t& r3,
                                        uint32_t addr)
{
    asm volatile("ldmatrix.sync.aligned.m8n8.x4.shared.b16 {%0,%1,%2,%3}, [%4];"
        : "=r"(r0), "=r"(r1), "=r"(r2), "=r"(r3) : "r"(addr));
}

// ---------------------------------------------------------------------------
// tf32 mma.sync GEMM: C[m,n] = sum_k A[m,k] * Bw[n,k]
// CTA 128x128, 8 warps of 32(M)x64(N), 3-stage cp.async, K stage = 16.
// Fragment loads via ldmatrix.x4 (b16 view of tf32, ROWP=20 -> conflict-free).
// ---------------------------------------------------------------------------
#define GM 128
#define GN 128
#define GKS 16
#define STAGES 3
#define ROWP 20
#define HALF_SLOT (128 * ROWP)
#define SLOT (2 * HALF_SLOT)
#define GEMM_SMEM (STAGES * SLOT * 4)

__global__ __launch_bounds__(256)
void gemm_tc_kernel(const float* __restrict__ A, const float* __restrict__ Bw,
                    float* __restrict__ C, int M, int N, int K)
{
    extern __shared__ float smem[];
    const uint32_t smem_base = smem_u32(smem);
    const int tid  = threadIdx.x;
    const int wid  = tid >> 5;
    const int lane = tid & 31;
    const int grp  = lane >> 2;
    const int qid  = lane & 3;
    const int m0 = blockIdx.y * GM;
    const int n0 = blockIdx.x * GN;
    const int nk = K / GKS;

    const int wm = (wid & 3) * 32;
    const int wn = (wid >> 2) * 64;

    // ldmatrix per-lane source offsets (bytes, relative to slot A/B base)
    const int m8  = lane >> 3;        // which 8x8 matrix this lane addresses
    const int rIn = lane & 7;         // row within matrix
    uint32_t aOff[2], bOff[4];
#pragma unroll
    for (int mi = 0; mi < 2; mi++)
        aOff[mi] = (uint32_t)(((wm + mi * 16 + (m8 & 1) * 8 + rIn) * ROWP + (m8 >> 1) * 4) * 4);
#pragma unroll
    for (int pi = 0; pi < 4; pi++)
        bOff[pi] = (uint32_t)(((wn + pi * 16 + ((m8 >> 1) & 1) * 8 + rIn) * ROWP + (m8 & 1) * 4) * 4);

    float d[2][8][4];
#pragma unroll
    for (int mi = 0; mi < 2; mi++)
#pragma unroll
        for (int ni = 0; ni < 8; ni++)
#pragma unroll
            for (int c = 0; c < 4; c++) d[mi][ni][c] = 0.0f;

    const int lr  = tid >> 1;
    const int lc0 = (tid & 1) * 2;

    auto load_stage = [&](int s) {
        const int slot = s % STAGES;
        const int k0 = s * GKS;
        const uint32_t abase = smem_base + slot * SLOT * 4;
        const uint32_t bbase = abase + HALF_SLOT * 4;
#pragma unroll
        for (int c = 0; c < 2; c++) {
            uint32_t soff = (uint32_t)(lr * ROWP + (lc0 + c) * 4) * 4;
            cp_async16(abase + soff, &A [(size_t)(m0 + lr) * K + k0 + (lc0 + c) * 4]);
            cp_async16(bbase + soff, &Bw[(size_t)(n0 + lr) * K + k0 + (lc0 + c) * 4]);
        }
        CP_COMMIT();
    };

    load_stage(0);
    load_stage(1);

    for (int s = 0; s < nk; s++) {
        CP_WAIT(1);
        __syncthreads();

        int ls = s + 2;
        if (ls < nk) load_stage(ls);

        const int slot = s % STAGES;
        const uint32_t sbase = smem_base + slot * SLOT * 4;
        const uint32_t bbase = sbase + HALF_SLOT * 4;

#pragma unroll
        for (int kk = 0; kk < GKS; kk += 8) {
            const uint32_t kb = (uint32_t)(kk * 4);
            uint32_t a[2][4], b[8][2];
            ldsm_x4(a[0][0], a[0][1], a[0][2], a[0][3], sbase + aOff[0] + kb);
            ldsm_x4(a[1][0], a[1][1], a[1][2], a[1][3], sbase + aOff[1] + kb);
#pragma unroll
            for (int pi = 0; pi < 4; pi++)
                ldsm_x4(b[2*pi][0], b[2*pi][1], b[2*pi+1][0], b[2*pi+1][1],
                        bbase + bOff[pi] + kb);
#pragma unroll
            for (int mi = 0; mi < 2; mi++)
#pragma unroll
                for (int ni = 0; ni < 8; ni++)
                    mma_tf32_m16n8k8(d[mi][ni][0], d[mi][ni][1], d[mi][ni][2], d[mi][ni][3],
                                     a[mi][0], a[mi][1], a[mi][2], a[mi][3],
                                     b[ni][0], b[ni][1]);
        }
    }

#pragma unroll
    for (int mi = 0; mi < 2; mi++) {
        int row = m0 + wm + mi * 16 + grp;
#pragma unroll
        for (int ni = 0; ni < 8; ni++) {
            int col = n0 + wn + ni * 8 + qid * 2;
            *(float2*)&C[(size_t)row * N + col]       = make_float2(d[mi][ni][0], d[mi][ni][1]);
            *(float2*)&C[(size_t)(row + 8) * N + col] = make_float2(d[mi][ni][2], d[mi][ni][3]);
        }
    }
}

// ---------------------------------------------------------------------------
// tf32 rna rounding (elementwise, float4)
// ---------------------------------------------------------------------------
__global__ __launch_bounds__(256)
void round_tf32_kernel(const float* __restrict__ in, float* __restrict__ out, int n4)
{
    int i = blockIdx.x * blockDim.x + threadIdx.x;
    if (i < n4) {
        float4 v = ((const float4*)in)[i];
        v.x = tf32r(v.x); v.y = tf32r(v.y); v.z = tf32r(v.z); v.w = tf32r(v.w);
        ((float4*)out)[i] = v;
    }
}

// ---------------------------------------------------------------------------
// RoPE + head split; outputs tf32-rounded; q pre-scaled by 1/sqrt(Dh)
// ---------------------------------------------------------------------------
__global__ __launch_bounds__(256)
void rope_split_kernel(const float* __restrict__ qkv,
                       float* __restrict__ q, float* __restrict__ k,
                       float* __restrict__ v)
{
    int idx = blockIdx.x * blockDim.x + threadIdx.x;
    int i = idx & 63;
    int h = (idx >> 6) & 15;
    int t = (idx >> 10) & 2047;
    int b = idx >> 21;

    int m = b * NT + t;
    const float* base = qkv + (size_t)m * (3 * ND);
    int col = h * DH + 2 * i;

    float q0 = base[col],          q1 = base[col + 1];
    float k0 = base[ND + col],     k1 = base[ND + col + 1];
    float v0 = base[2*ND + col],   v1 = base[2*ND + col + 1];

    float fr = expf(-logf(10000.0f) * (2.0f * (float)i) / (float)DH);
    float ang = (float)t * fr;
    float sn = sinf(ang), cs = cosf(ang);
    const float scale = 0.08838834764831845f;   // 1/sqrt(128)

    size_t o = ((size_t)(b * NH + h) * NT + t) * DH + 2 * i;
    q[o]     = tf32r((q0 * cs - q1 * sn) * scale);
    q[o + 1] = tf32r((q1 * cs + q0 * sn) * scale);
    k[o]     = tf32r(k0 * cs - k1 * sn);
    k[o + 1] = tf32r(k1 * cs + k0 * sn);
    v[o]     = tf32r(v0);
    v[o + 1] = tf32r(v1);
}

// ---------------------------------------------------------------------------
// Tensor-core causal flash attention (tf32 mma.sync).  (unchanged from R8)
// ---------------------------------------------------------------------------
#define AQ 64
#define AK 64
#define QPAD 140
#define KPAD 140
#define VPAD 136
#define PPAD 76

#define QS_OFF 0
#define KS_OFF 8960
#define VS_OFF 26880
#define PS_OFF 44288
#define PM_OFF 49152
#define PL_OFF 49280
#define ATTN_FLOATS 49408
#define ATTN_SMEM (ATTN_FLOATS * 4)

__global__ __launch_bounds__(256, 1)
void attn_tc_kernel(const float* __restrict__ Q, const float* __restrict__ K,
                    const float* __restrict__ V, float* __restrict__ O)
{
    extern __shared__ float sm[];
    const uint32_t smem_base = smem_u32(sm);
    uint32_t* smU = reinterpret_cast<uint32_t*>(sm);

    const int tid  = threadIdx.x;
    const int wid  = tid >> 5;
    const int lane = tid & 31;
    const int grp  = lane >> 2;
    const int qid  = lane & 3;
    const int ws   = wid & 3;
    const int wn   = wid >> 2;

    const int qt = blockIdx.x;
    const int h  = blockIdx.y;
    const int b  = blockIdx.z;
    const size_t head_base = (size_t)(b * NH + h) * NT * DH;

    {
        const float* qb = Q + head_base + (size_t)qt * AQ * DH;
#pragma unroll
        for (int u = 0; u < 8; u++) {
            int e = tid + u * 256;
            int r = e >> 5;
            int c4 = (e & 31) * 4;
            *(float4*)&sm[QS_OFF + r * QPAD + c4] = *(const float4*)&qb[(size_t)r * DH + c4];
        }
    }

    auto load_kv = [&](int tile, int buf) {
        const float* kb = K + head_base + (size_t)tile * AK * DH;
        const float* vb = V + head_base + (size_t)tile * AK * DH;
#pragma unroll
        for (int u = 0; u < 8; u++) {
            int e = tid + u * 256;
            int r = e >> 5;
            int c4 = (e & 31) * 4;
            cp_async16(smem_base + (uint32_t)(KS_OFF + buf * (AK*KPAD) + r * KPAD + c4) * 4,
                       &kb[(size_t)r * DH + c4]);
            cp_async16(smem_base + (uint32_t)(VS_OFF + buf * (AK*VPAD) + r * VPAD + c4) * 4,
                       &vb[(size_t)r * DH + c4]);
        }
        CP_COMMIT();
    };
    load_kv(0, 0);
    __syncthreads();

    const int row0 = ws * 16 + grp;
    const int row1 = row0 + 8;
    uint32_t Qf[16][4];
#pragma unroll
    for (int s = 0; s < 16; s++) {
        int c = s * 8 + qid;
        Qf[s][0] = smU[QS_OFF + row0 * QPAD + c];
        Qf[s][1] = smU[QS_OFF + row1 * QPAD + c];
        Qf[s][2] = smU[QS_OFF + row0 * QPAD + c + 4];
        Qf[s][3] = smU[QS_OFF + row1 * QPAD + c + 4];
    }

    float accO[8][4];
#pragma unroll
    for (int ni = 0; ni < 8; ni++)
#pragma unroll
        for (int c = 0; c < 4; c++) accO[ni][c] = 0.0f;
    float m0 = -1e30f, m1 = -1e30f, l0 = 0.0f, l1 = 0.0f;

    for (int kt = 0; kt <= qt; kt++) {
        const int buf = kt & 1;
        if (kt < qt) { load_kv(kt + 1, buf ^ 1); CP_WAIT(1); }
        else         { CP_WAIT(0); }
        __syncthreads();

        float sa[4][4];
#pragma unroll
        for (int ni = 0; ni < 4; ni++)
#pragma unroll
            for (int c = 0; c < 4; c++) sa[ni][c] = 0.0f;

        const uint32_t* Ks = smU + KS_OFF + buf * (AK*KPAD);
#pragma unroll
        for (int s = 0; s < 16; s++) {
            int kk = s * 8;
            uint32_t b0[4], b1[4];
#pragma unroll
            for (int ni = 0; ni < 4; ni++) {
                int kr = wn * 32 + ni * 8 + grp;
                b0[ni] = Ks[kr * KPAD + kk + qid];
                b1[ni] = Ks[kr * KPAD + kk + qid + 4];
            }
#pragma unroll
            for (int ni = 0; ni < 4; ni++)
                mma_tf32_m16n8k8(sa[ni][0], sa[ni][1], sa[ni][2], sa[ni][3],
                                 Qf[s][0], Qf[s][1], Qf[s][2], Qf[s][3],
                                 b0[ni], b1[ni]);
        }

        if (kt == qt) {
#pragma unroll
            for (int ni = 0; ni < 4; ni++) {
                int cl = wn * 32 + ni * 8 + 2 * qid;
                if (cl     > row0) sa[ni][0] = -1e30f;
                if (cl + 1 > row0) sa[ni][1] = -1e30f;
                if (cl     > row1) sa[ni][2] = -1e30f;
                if (cl + 1 > row1) sa[ni][3] = -1e30f;
            }
        }

        float pm0 = -1e30f, pm1 = -1e30f;
#pragma unroll
        for (int ni = 0; ni < 4; ni++) {
            pm0 = fmaxf(pm0, fmaxf(sa[ni][0], sa[ni][1]));
            pm1 = fmaxf(pm1, fmaxf(sa[ni][2], sa[ni][3]));
        }
        pm0 = fmaxf(pm0, __shfl_xor_sync(0xffffffffu, pm0, 1));
        pm0 = fmaxf(pm0, __shfl_xor_sync(0xffffffffu, pm0, 2));
        pm1 = fmaxf(pm1, __shfl_xor_sync(0xffffffffu, pm1, 1));
        pm1 = fmaxf(pm1, __shfl_xor_sync(0xffffffffu, pm1, 2));
        if (qid == 0) {
            sm[PM_OFF + row0 * 2 + wn] = pm0;
            sm[PM_OFF + row1 * 2 + wn] = pm1;
        }
        __syncthreads();

        float mn0 = fmaxf(m0, fmaxf(sm[PM_OFF + row0 * 2], sm[PM_OFF + row0 * 2 + 1]));
        float mn1 = fmaxf(m1, fmaxf(sm[PM_OFF + row1 * 2], sm[PM_OFF + row1 * 2 + 1]));

        float ps0 = 0.0f, ps1 = 0.0f;
#pragma unroll
        for (int ni = 0; ni < 4; ni++) {
            float p00 = __expf(sa[ni][0] - mn0);
            float p01 = __expf(sa[ni][1] - mn0);
            float p10 = __expf(sa[ni][2] - mn1);
            float p11 = __expf(sa[ni][3] - mn1);
            ps0 += p00 + p01;
            ps1 += p10 + p11;
            int cl = wn * 32 + ni * 8 + 2 * qid;
            *(float2*)&sm[PS_OFF + row0 * PPAD + cl] = make_float2(tf32r(p00), tf32r(p01));
            *(float2*)&sm[PS_OFF + row1 * PPAD + cl] = make_float2(tf32r(p10), tf32r(p11));
        }
        ps0 += __shfl_xor_sync(0xffffffffu, ps0, 1);
        ps0 += __shfl_xor_sync(0xffffffffu, ps0, 2);
        ps1 += __shfl_xor_sync(0xffffffffu, ps1, 1);
        ps1 += __shfl_xor_sync(0xffffffffu, ps1, 2);
        if (qid == 0) {
            sm[PL_OFF + row0 * 2 + wn] = ps0;
            sm[PL_OFF + row1 * 2 + wn] = ps1;
        }
        __syncthreads();

        float fac0 = __expf(m0 - mn0);
        float fac1 = __expf(m1 - mn1);
        m0 = mn0; m1 = mn1;
        l0 = l0 * fac0 + sm[PL_OFF + row0 * 2] + sm[PL_OFF + row0 * 2 + 1];
        l1 = l1 * fac1 + sm[PL_OFF + row1 * 2] + sm[PL_OFF + row1 * 2 + 1];

#pragma unroll
        for (int ni = 0; ni < 8; ni++) {
            accO[ni][0] *= fac0; accO[ni][1] *= fac0;
            accO[ni][2] *= fac1; accO[ni][3] *= fac1;
        }

        const uint32_t* Vs = smU + VS_OFF + buf * (AK*VPAD);
#pragma unroll
        for (int s8 = 0; s8 < 8; s8++) {
            int kk = s8 * 8;
            uint32_t a0 = smU[PS_OFF + row0 * PPAD + kk + qid];
            uint32_t a1 = smU[PS_OFF + row1 * PPAD + kk + qid];
            uint32_t a2 = smU[PS_OFF + row0 * PPAD + kk + qid + 4];
            uint32_t a3 = smU[PS_OFF + row1 * PPAD + kk + qid + 4];
#pragma unroll
            for (int ni = 0; ni < 8; ni++) {
                int vc = wn * 64 + ni * 8 + grp;
                uint32_t b0 = Vs[(kk + qid) * VPAD + vc];
                uint32_t b1 = Vs[(kk + qid + 4) * VPAD + vc];
                mma_tf32_m16n8k8(accO[ni][0], accO[ni][1], accO[ni][2], accO[ni][3],
                                 a0, a1, a2, a3, b0, b1);
            }
        }
        __syncthreads();
    }

    float inv0 = 1.0f / l0, inv1 = 1.0f / l1;
    int t0 = qt * AQ + row0;
    int t1 = qt * AQ + row1;
#pragma unroll
    for (int ni = 0; ni < 8; ni++) {
        int col = h * DH + wn * 64 + ni * 8 + 2 * qid;
        *(float2*)&O[(size_t)(b * NT + t0) * ND + col] =
            make_float2(tf32r(accO[ni][0] * inv0), tf32r(accO[ni][1] * inv0));
        *(float2*)&O[(size_t)(b * NT + t1) * ND + col] =
            make_float2(tf32r(accO[ni][2] * inv1), tf32r(accO[ni][3] * inv1));
    }
}

// ---------------------------------------------------------------------------
extern "C" void kernel_launch(void* const* d_in, const int* in_sizes, int n_in,
                              void* d_out, int out_size)
{
    const float* x    = (const float*)d_in[0];
    const float* Wqkv = (const float*)d_in[1];
    const float* WO   = (const float*)d_in[2];
    float* out = (float*)d_out;

    float *qkv, *q, *k, *v, *att, *xr, *wr, *wor;
    cudaGetSymbolAddress((void**)&qkv, g_qkv);
    cudaGetSymbolAddress((void**)&q,   g_q);
    cudaGetSymbolAddress((void**)&k,   g_k);
    cudaGetSymbolAddress((void**)&v,   g_v);
    cudaGetSymbolAddress((void**)&att, g_att);
    cudaGetSymbolAddress((void**)&xr,  g_xr);
    cudaGetSymbolAddress((void**)&wr,  g_wqkvr);
    cudaGetSymbolAddress((void**)&wor, g_wor);

    // 0) tf32-round GEMM operands
    round_tf32_kernel<<<(NM*ND/4)/256, 256>>>(x, xr, NM*ND/4);
    round_tf32_kernel<<<(3*ND*ND/4)/256, 256>>>(Wqkv, wr, 3*ND*ND/4);
    round_tf32_kernel<<<(ND*ND/4)/256, 256>>>(WO, wor, ND*ND/4);

    // 1) QKV projection (tf32 mma.sync + ldmatrix)
    cudaFuncSetAttribute(gemm_tc_kernel, cudaFuncAttributeMaxDynamicSharedMemorySize, GEMM_SMEM);
    gemm_tc_kernel<<<dim3(3*ND/GN, NM/GM), 256, GEMM_SMEM>>>(xr, wr, qkv, NM, 3*ND, ND);

    // 2) RoPE + head split (tf32 outputs, q pre-scaled)
    rope_split_kernel<<<(NB*NT*NH*64)/256, 256>>>(qkv, q, k, v);

    // 3) Tensor-core causal flash attention
    cudaFuncSetAttribute(attn_tc_kernel, cudaFuncAttributeMaxDynamicSharedMemorySize, ATTN_SMEM);
    attn_tc_kernel<<<dim3(NT/AQ, NH, NB), 256, ATTN_SMEM>>>(q, k, v, att);

    // 4) Output projection (tf32 mma.sync + ldmatrix)
    gemm_tc_kernel<<<dim3(ND/GN, NM/GM), 256, GEMM_SMEM>>>(att, wor, out, NM, ND, ND);
}